// round 3
// baseline (speedup 1.0000x reference)
#include <cuda_runtime.h>
#include <math.h>

// Problem constants
#define BB 32
#define LL 2880
#define CC 862
#define PREDP 720
#define SEGS 48
#define NMM 4
#define KK 16
#define STRIDEV 8
#define NINV 60
#define NOUTV 15
#define CDIMV 359

#define CPB 8              // channels per block
#define XROW 2884          // padded smem row length (floats)
#define NTHR 512
#define CBLKS ((CC + CPB - 1) / CPB)   // 108

// dynamic smem layout (floats):
//   xs   : CPB*XROW = 23072
//   wbuf : 3600   (phase1: 2048 partials | phase3: 1436 gate_w + 2048 partials @1536 | phase4: 3600 W_eff)
//   cw   : 128, gts : 32, meanv/stdv/istdv : 8 each, beff : 60, cbs : 8
#define SMEM_FLOATS (CPB*XROW + 3600 + 128 + 32 + 8 + 8 + 8 + 60 + 8)

__global__ __launch_bounds__(NTHR, 2)
void fused_model_kernel(const float* __restrict__ x,
                        const float* __restrict__ conv_w,
                        const float* __restrict__ conv_b,
                        const float* __restrict__ gate_w,
                        const float* __restrict__ gate_b,
                        const float* __restrict__ map_w,
                        const float* __restrict__ map_b,
                        float* __restrict__ out)
{
    extern __shared__ float sm[];
    float* xs    = sm;                    // 23072
    float* wbuf  = xs + CPB * XROW;       // 3600
    float* cw    = wbuf + 3600;           // 128
    float* gts   = cw + 128;              // 32
    float* meanv = gts + 32;              // 8
    float* stdv  = meanv + 8;             // 8
    float* istdv = stdv + 8;              // 8
    float* beff  = istdv + 8;             // 60
    float* cbs   = beff + 60;             // 8

    const int t  = threadIdx.x;
    const int b  = blockIdx.x / CBLKS;
    const int c0 = (blockIdx.x % CBLKS) * CPB;

    // ---- phase 0: per-channel conv weights/bias ----
    if (t < CPB * KK) {
        int ch = t >> 4, k = t & 15;
        int c = c0 + ch;
        cw[t] = (c < CC) ? conv_w[c * KK + k] : 0.f;
    }
    if (t >= 128 && t < 128 + CPB) {
        int c = c0 + (t - 128);
        cbs[t - 128] = (c < CC) ? conv_b[c] : 0.f;
    }

    // ---- phase 1: load x slice (float2, channel pairs) + stats partials ----
    {
        const int pr   = t & 3;           // channel pair 0..3
        const int lane = t >> 2;          // 0..127
        const int c    = c0 + pr * 2;
        const bool v0 = (c < CC), v1 = (c + 1 < CC);
        const float* xb = x + (size_t)b * LL * CC + c;
        float* r0 = xs + (pr * 2) * XROW;
        float* r1 = r0 + XROW;
        float s0 = 0.f, q0 = 0.f, s1 = 0.f, q1 = 0.f;
        if (v1) {
            #pragma unroll 4
            for (int l = lane; l < LL; l += 128) {
                float2 vv = *(const float2*)(xb + (size_t)l * CC);
                r0[l] = vv.x; r1[l] = vv.y;
                s0 += vv.x; q0 = fmaf(vv.x, vv.x, q0);
                s1 += vv.y; q1 = fmaf(vv.y, vv.y, q1);
            }
        } else {
            for (int l = lane; l < LL; l += 128) {
                float a = v0 ? __ldg(xb + (size_t)l * CC) : 0.f;
                r0[l] = a; r1[l] = 0.f;
                s0 += a; q0 = fmaf(a, a, q0);
            }
        }
        int ch = pr * 2;
        wbuf[ch * 128 + lane]            = s0;
        wbuf[1024 + ch * 128 + lane]     = q0;
        wbuf[(ch + 1) * 128 + lane]        = s1;
        wbuf[1024 + (ch + 1) * 128 + lane] = q1;
    }
    __syncthreads();
    if (t < 256) {       // one warp per channel
        int ch = t >> 5, j = t & 31;
        float s  = wbuf[ch * 128 + j] + wbuf[ch * 128 + j + 32]
                 + wbuf[ch * 128 + j + 64] + wbuf[ch * 128 + j + 96];
        float s2 = wbuf[1024 + ch * 128 + j] + wbuf[1024 + ch * 128 + j + 32]
                 + wbuf[1024 + ch * 128 + j + 64] + wbuf[1024 + ch * 128 + j + 96];
        #pragma unroll
        for (int off = 16; off; off >>= 1) {
            s  += __shfl_down_sync(0xffffffff, s,  off);
            s2 += __shfl_down_sync(0xffffffff, s2, off);
        }
        if (j == 0) {
            float mean = s * (1.f / LL);
            float var  = fmaxf(s2 * (1.f / LL) - mean * mean, 0.f);
            float sd   = sqrtf(var + 1e-10f);
            meanv[ch] = mean;
            stdv[ch]  = sd;
            istdv[ch] = 1.f / sd;
        }
    }
    __syncthreads();

    // ---- phase 2: normalize in place (float4) ----
    {
        const int ch = t >> 6, q0i = t & 63;
        const float mean = meanv[ch], is = istdv[ch];
        float4* row4 = (float4*)(xs + ch * XROW);
        #pragma unroll 3
        for (int q = q0i; q < LL / 4; q += 64) {
            float4 v = row4[q];
            v.x = (v.x - mean) * is;
            v.y = (v.y - mean) * is;
            v.z = (v.z - mean) * is;
            v.w = (v.w - mean) * is;
            row4[q] = v;
        }
    }
    // stage gate_w into smem (wbuf[0..1435]), partials live at wbuf+1536
    for (int i = t; i < NMM * CDIMV; i += NTHR)
        wbuf[i] = __ldg(gate_w + i);
    __syncthreads();

    // ---- phase 3: depthwise conv + gate logit partials ----
    {
        const int ch = t >> 6, dl = t & 63;   // 64 d-lanes per channel
        const float4* kwp = (const float4*)(cw + ch * 16);
        const float4 kA = kwp[0], kB = kwp[1], kC = kwp[2], kD = kwp[3];
        const float cb = cbs[ch];
        const float* row = xs + ch * XROW;
        const float* gws = wbuf;
        float a0 = 0.f, a1 = 0.f, a2 = 0.f, a3 = 0.f;
        #pragma unroll
        for (int j = 0; j < 6; j++) {
            int d = dl + 64 * j;
            if (d < CDIMV) {
                const float4* base = (const float4*)(row + 8 * d);
                float4 w0 = base[0], w1 = base[1], w2 = base[2], w3 = base[3];
                float cv = cb;
                cv = fmaf(w0.x, kA.x, cv); cv = fmaf(w0.y, kA.y, cv);
                cv = fmaf(w0.z, kA.z, cv); cv = fmaf(w0.w, kA.w, cv);
                cv = fmaf(w1.x, kB.x, cv); cv = fmaf(w1.y, kB.y, cv);
                cv = fmaf(w1.z, kB.z, cv); cv = fmaf(w1.w, kB.w, cv);
                cv = fmaf(w2.x, kC.x, cv); cv = fmaf(w2.y, kC.y, cv);
                cv = fmaf(w2.z, kC.z, cv); cv = fmaf(w2.w, kC.w, cv);
                cv = fmaf(w3.x, kD.x, cv); cv = fmaf(w3.y, kD.y, cv);
                cv = fmaf(w3.z, kD.z, cv); cv = fmaf(w3.w, kD.w, cv);
                a0 = fmaf(cv, gws[d],             a0);
                a1 = fmaf(cv, gws[CDIMV + d],     a1);
                a2 = fmaf(cv, gws[2 * CDIMV + d], a2);
                a3 = fmaf(cv, gws[3 * CDIMV + d], a3);
            }
        }
        float* rp = wbuf + 1536 + ch * 256 + dl * 4;
        rp[0] = a0; rp[1] = a1; rp[2] = a2; rp[3] = a3;
    }
    __syncthreads();
    if (t < 32) {
        int ch = t >> 2, m = t & 3;
        float s = 0.f;
        #pragma unroll
        for (int dl = 0; dl < 64; dl++) s += wbuf[1536 + ch * 256 + dl * 4 + m];
        gts[ch * 4 + m] = s + __ldg(gate_b + m);
    }
    __syncthreads();
    if (t < CPB) {
        float g0 = gts[t * 4], g1 = gts[t * 4 + 1], g2 = gts[t * 4 + 2], g3 = gts[t * 4 + 3];
        float mx = fmaxf(fmaxf(g0, g1), fmaxf(g2, g3));
        g0 = expf(g0 - mx); g1 = expf(g1 - mx); g2 = expf(g2 - mx); g3 = expf(g3 - mx);
        float inv = 1.f / (g0 + g1 + g2 + g3);
        gts[t * 4]     = g0 * inv;
        gts[t * 4 + 1] = g1 * inv;
        gts[t * 4 + 2] = g2 * inv;
        gts[t * 4 + 3] = g3 * inv;
    }
    __syncthreads();

    // ---- phase 4: two groups of 4 channels: W_eff, map matmul, stage ----
    #pragma unroll 1
    for (int g = 0; g < 2; g++) {
        for (int p = t; p < NOUTV * NINV; p += NTHR) {
            float m0 = __ldg(map_w + p);
            float m1 = __ldg(map_w + 900 + p);
            float m2 = __ldg(map_w + 1800 + p);
            float m3 = __ldg(map_w + 2700 + p);
            #pragma unroll
            for (int c4 = 0; c4 < 4; c4++) {
                const float* gg = gts + (g * 4 + c4) * 4;
                wbuf[c4 * 900 + p] = gg[0] * m0 + gg[1] * m1 + gg[2] * m2 + gg[3] * m3;
            }
        }
        if (t < 60) {
            int c4 = t / 15, o = t % 15;
            const float* gg = gts + (g * 4 + c4) * 4;
            beff[t] = gg[0] * __ldg(map_b + o)      + gg[1] * __ldg(map_b + 15 + o)
                    + gg[2] * __ldg(map_b + 30 + o) + gg[3] * __ldg(map_b + 45 + o);
        }
        __syncthreads();

        // register-tiled matmul: tile = 3 outputs (o) x 2 preds (float2)
        float2 acc0, acc1, acc2;
        int ch4 = 0, o0 = 0, sp = 0;
        const bool active = (t < 480);
        if (active) {
            ch4 = t / 120;
            int rem = t % 120;
            o0 = (rem / 24) * 3;
            sp = rem % 24;
            const float* row = xs + (g * 4 + ch4) * XROW + sp * 2;
            const float* W0 = wbuf + ch4 * 900 + o0 * 60;
            acc0 = make_float2(0.f, 0.f);
            acc1 = acc0; acc2 = acc0;
            #pragma unroll 10
            for (int i = 0; i < NINV; i++) {
                float2 xv = *(const float2*)(row + i * SEGS);
                float w0 = W0[i], w1 = W0[60 + i], w2 = W0[120 + i];
                acc0.x = fmaf(w0, xv.x, acc0.x);
                acc0.y = fmaf(w0, xv.y, acc0.y);
                acc1.x = fmaf(w1, xv.x, acc1.x);
                acc1.y = fmaf(w1, xv.y, acc1.y);
                acc2.x = fmaf(w2, xv.x, acc2.x);
                acc2.y = fmaf(w2, xv.y, acc2.y);
            }
        }
        __syncthreads();   // all xn/W_eff reads done before staging overwrites xs
        if (active) {
            int ch = g * 4 + ch4;
            float sd = stdv[ch], mu = meanv[ch];
            float* orow = xs + ch * XROW;
            float b0 = beff[ch4 * 15 + o0];
            float b1 = beff[ch4 * 15 + o0 + 1];
            float b2 = beff[ch4 * 15 + o0 + 2];
            float2 r;
            r.x = fmaf(acc0.x + b0, sd, mu);
            r.y = fmaf(acc0.y + b0, sd, mu);
            *(float2*)(orow + (o0 + 0) * SEGS + sp * 2) = r;
            r.x = fmaf(acc1.x + b1, sd, mu);
            r.y = fmaf(acc1.y + b1, sd, mu);
            *(float2*)(orow + (o0 + 1) * SEGS + sp * 2) = r;
            r.x = fmaf(acc2.x + b2, sd, mu);
            r.y = fmaf(acc2.y + b2, sd, mu);
            *(float2*)(orow + (o0 + 2) * SEGS + sp * 2) = r;
        }
        __syncthreads();   // group done; wbuf free for next group
    }

    // ---- phase 5: coalesced output write (float2, 2 channels) ----
    {
        const size_t obase = (size_t)b * PREDP * CC + c0;
        for (int idx = t; idx < 4 * PREDP; idx += NTHR) {
            int pr = idx & 3, p = idx >> 2;
            int c = c0 + pr * 2;
            float2 v;
            v.x = xs[(pr * 2) * XROW + p];
            v.y = xs[(pr * 2 + 1) * XROW + p];
            if (c + 1 < CC)
                *(float2*)(out + obase + (size_t)p * CC + pr * 2) = v;
            else if (c < CC)
                out[obase + (size_t)p * CC + pr * 2] = v.x;
        }
    }
}

extern "C" void kernel_launch(void* const* d_in, const int* in_sizes, int n_in,
                              void* d_out, int out_size)
{
    const float* x      = (const float*)d_in[0];
    const float* conv_w = (const float*)d_in[1];
    const float* conv_b = (const float*)d_in[2];
    const float* gate_w = (const float*)d_in[3];
    const float* gate_b = (const float*)d_in[4];
    const float* map_w  = (const float*)d_in[5];
    const float* map_b  = (const float*)d_in[6];
    float* out = (float*)d_out;

    const int smem_bytes = SMEM_FLOATS * (int)sizeof(float);   // 107,696 B
    cudaFuncSetAttribute(fused_model_kernel,
                         cudaFuncAttributeMaxDynamicSharedMemorySize, smem_bytes);

    dim3 grid(BB * CBLKS);   // 3456 blocks
    fused_model_kernel<<<grid, NTHR, smem_bytes>>>(x, conv_w, conv_b, gate_w,
                                                   gate_b, map_w, map_b, out);
}